// round 2
// baseline (speedup 1.0000x reference)
#include <cuda_runtime.h>
#include <cstdint>

// ---------------------------------------------------------------------------
// QuadTreeDecoder (fp32, round 2)
//   levels 0-4: qt_level_small — block = node, 512 thr = (4 children x 128 batch)
//   level 5 + head: fused — block = parent node, 128 thr = batch; children never
//                   hit DRAM, head contraction runs straight out of registers.
// Activation layout stays b-major: act[b][node][64].
// ---------------------------------------------------------------------------

#define B_SZ 128

// ping-pong activation buffers (device globals; allocation is forbidden)
__device__ float g_buf0[(size_t)B_SZ * 1024 * 64];   // 33.5 MB (levels 0,2,4 out)
__device__ float g_buf1[(size_t)B_SZ * 256  * 64];   //  8.4 MB (levels 1,3 out)

// ---------------------------------------------------------------------------
// Levels 0..4: block = one node, 512 threads = child c (tid>>7) x batch b (tid&127)
// Each child-group recomputes lat (redundant but these levels are latency-bound).
// ---------------------------------------------------------------------------
__global__ __launch_bounds__(512)
void qt_level_small(const float* __restrict__ xin, float* __restrict__ xout,
                    const float* __restrict__ fin,
                    const float* __restrict__ ftl, const float* __restrict__ ftr,
                    const float* __restrict__ fbl, const float* __restrict__ fbr,
                    const float* __restrict__ scale,
                    int n, int off, int gside)
{
    __shared__ float fi_s[16][64];      // [r][i]  (rows 256B aligned -> LDS.128)
    __shared__ float F_s[4][16][64];    // [child][r][o] (natural layout: conflict-free staging)
    __shared__ float sc_s[16];

    const int p    = blockIdx.x;
    const int tid  = threadIdx.x;
    const int node = off + p;

    const float* fib = fin + (size_t)node * 1024;
    for (int k = tid; k < 1024; k += 512)
        fi_s[k >> 6][k & 63] = fib[k];

    {
        const float* srcs0 = ftl + (size_t)node * 1024;
        const float* srcs1 = ftr + (size_t)node * 1024;
        const float* srcs2 = fbl + (size_t)node * 1024;
        const float* srcs3 = fbr + (size_t)node * 1024;
        for (int k = tid; k < 1024; k += 512) {
            F_s[0][k >> 6][k & 63] = srcs0[k];
            F_s[1][k >> 6][k & 63] = srcs1[k];
            F_s[2][k >> 6][k & 63] = srcs2[k];
            F_s[3][k >> 6][k & 63] = srcs3[k];
        }
    }
    if (tid < 16) sc_s[tid] = scale[(size_t)node * 16 + tid];
    __syncthreads();

    const int c = tid >> 7;      // child 0..3
    const int b = tid & 127;     // batch
    const float* xp = xin + ((size_t)b * n + p) * 64;

    // lat[r] = scale[r] * dot(x, fi[r,:])   — float4 LDS, 1 LDS : 4 FMA
    float lat[16];
#pragma unroll
    for (int r = 0; r < 16; r++) lat[r] = 0.f;
#pragma unroll 1
    for (int i = 0; i < 64; i += 4) {
        float4 xv = *(const float4*)(xp + i);
#pragma unroll
        for (int r = 0; r < 16; r++) {
            float4 f = *(const float4*)&fi_s[r][i];
            lat[r] += xv.x * f.x + xv.y * f.y + xv.z * f.z + xv.w * f.w;
        }
    }
#pragma unroll
    for (int r = 0; r < 16; r++) lat[r] *= sc_s[r];

    // child output: out[o] = x[o] + sum_r lat[r] * F[c][r][o]
    const int gr = p / gside;
    const int gc = p - gr * gside;
    const int cn = (2 * gr + (c >> 1)) * (2 * gside) + 2 * gc + (c & 1);
    float* op = xout + ((size_t)b * (4 * n) + cn) * 64;

#pragma unroll 1
    for (int o = 0; o < 64; o += 4) {
        float4 ov = *(const float4*)(xp + o);    // residual (L1 hit)
#pragma unroll
        for (int r = 0; r < 16; r++) {
            float4 f = *(const float4*)&F_s[c][r][o];
            float l = lat[r];
            ov.x += l * f.x; ov.y += l * f.y; ov.z += l * f.z; ov.w += l * f.w;
        }
        *(float4*)(op + o) = ov;
    }
}

// ---------------------------------------------------------------------------
// Fused level 5 + head. Block = one level-5 parent node (grid 1024),
// 128 threads = batch. Children live only in registers.
// ---------------------------------------------------------------------------
__global__ __launch_bounds__(128)
void qt_l5_head(const float* __restrict__ xin,
                const float* __restrict__ fin,
                const float* __restrict__ ftl, const float* __restrict__ ftr,
                const float* __restrict__ fbl, const float* __restrict__ fbr,
                const float* __restrict__ scale,
                const float* __restrict__ head_w,
                const float* __restrict__ head_b,
                float* __restrict__ out)
{
    __shared__ float fi_s[16][64];
    __shared__ float F_s[4][16][64];
    __shared__ float w_s[48][64];
    __shared__ float sc_s[16];
    __shared__ float hb_s[48];

    const int p    = blockIdx.x;     // 0..1023, gside = 32
    const int tid  = threadIdx.x;    // batch
    const int node = 341 + p;

    const float* fib = fin + (size_t)node * 1024;
    for (int k = tid; k < 1024; k += 128)
        fi_s[k >> 6][k & 63] = fib[k];
    {
        const float* s0 = ftl + (size_t)node * 1024;
        const float* s1 = ftr + (size_t)node * 1024;
        const float* s2 = fbl + (size_t)node * 1024;
        const float* s3 = fbr + (size_t)node * 1024;
        for (int k = tid; k < 1024; k += 128) {
            F_s[0][k >> 6][k & 63] = s0[k];
            F_s[1][k >> 6][k & 63] = s1[k];
            F_s[2][k >> 6][k & 63] = s2[k];
            F_s[3][k >> 6][k & 63] = s3[k];
        }
    }
    for (int k = tid; k < 48 * 64; k += 128)
        w_s[k >> 6][k & 63] = head_w[k];
    if (tid < 16) sc_s[tid] = scale[(size_t)node * 16 + tid];
    if (tid < 48) hb_s[tid] = head_b[tid];
    __syncthreads();

    const int b = tid;
    const float* xp = xin + ((size_t)b * 1024 + p) * 64;

    // lat
    float lat[16];
#pragma unroll
    for (int r = 0; r < 16; r++) lat[r] = 0.f;
#pragma unroll 1
    for (int i = 0; i < 64; i += 4) {
        float4 xv = *(const float4*)(xp + i);
#pragma unroll
        for (int r = 0; r < 16; r++) {
            float4 f = *(const float4*)&fi_s[r][i];
            lat[r] += xv.x * f.x + xv.y * f.y + xv.z * f.z + xv.w * f.w;
        }
    }
#pragma unroll
    for (int r = 0; r < 16; r++) lat[r] *= sc_s[r];

    const int gr = p >> 5;
    const int gc = p & 31;

#pragma unroll 1
    for (int c = 0; c < 4; c++) {
        const int cn = (2 * gr + (c >> 1)) * 64 + 2 * gc + (c & 1);

        float acc[48];
#pragma unroll
        for (int k = 0; k < 48; k++) acc[k] = hb_s[k];

        // stream child activation 4 floats at a time straight into the head
#pragma unroll 1
        for (int o = 0; o < 64; o += 4) {
            float4 ov = *(const float4*)(xp + o);   // residual (L1 hit)
#pragma unroll
            for (int r = 0; r < 16; r++) {
                float4 f = *(const float4*)&F_s[c][r][o];
                float l = lat[r];
                ov.x += l * f.x; ov.y += l * f.y; ov.z += l * f.z; ov.w += l * f.w;
            }
#pragma unroll
            for (int k = 0; k < 48; k++) {
                float4 wv = *(const float4*)&w_s[k][o];
                acc[k] += ov.x * wv.x + ov.y * wv.y + ov.z * wv.z + ov.w * wv.w;
            }
        }

        // y[b, cn, k] -> pixels. k = pr*12 + pc*3 + oc
        const int sr = cn >> 6, sc = cn & 63;
#pragma unroll
        for (int oc = 0; oc < 3; oc++) {
#pragma unroll
            for (int pr = 0; pr < 4; pr++) {
                float4 v = make_float4(acc[pr * 12 + 0 + oc],
                                       acc[pr * 12 + 3 + oc],
                                       acc[pr * 12 + 6 + oc],
                                       acc[pr * 12 + 9 + oc]);
                size_t row = (size_t)(b * 3 + oc) * 256 + (sr * 4 + pr);
                *(float4*)(out + row * 256 + sc * 4) = v;
            }
        }
    }
}

// ---------------------------------------------------------------------------
extern "C" void kernel_launch(void* const* d_in, const int* in_sizes, int n_in,
                              void* d_out, int out_size)
{
    const float* x      = (const float*)d_in[0];
    const float* fin    = (const float*)d_in[1];
    const float* ftl    = (const float*)d_in[2];
    const float* ftr    = (const float*)d_in[3];
    const float* fbl    = (const float*)d_in[4];
    const float* fbr    = (const float*)d_in[5];
    const float* scale  = (const float*)d_in[6];
    const float* head_w = (const float*)d_in[7];
    const float* head_b = (const float*)d_in[8];
    float* out = (float*)d_out;

    float *b0, *b1;
    cudaGetSymbolAddress((void**)&b0, g_buf0);
    cudaGetSymbolAddress((void**)&b1, g_buf1);

    const int ns[5]   = {1, 4, 16, 64, 256};
    const int offs[5] = {0, 1, 5, 21, 85};
    const int gs[5]   = {1, 2, 4, 8, 16};

    // levels 0..4 : out buffers  b0, b1, b0, b1, b0
    const float* cur = x;
    for (int l = 0; l < 5; l++) {
        float* o = (l & 1) ? b1 : b0;
        qt_level_small<<<ns[l], 512>>>(cur, o, fin, ftl, ftr, fbl, fbr, scale,
                                       ns[l], offs[l], gs[l]);
        cur = o;
    }

    // fused level 5 + head
    qt_l5_head<<<1024, 128>>>(cur, fin, ftl, ftr, fbl, fbr, scale,
                              head_w, head_b, out);
}

// round 3
// speedup vs baseline: 1.4297x; 1.4297x over previous
#include <cuda_runtime.h>
#include <cstdint>

// ---------------------------------------------------------------------------
// QuadTreeDecoder round 3
//   key identity:  y = W(x + F_c^T lat) + b  =  (W x + b) + (W F_c^T) lat
//   -> precompute WF[p][c] = W * F_c^T (48x16 per node-child) once per launch,
//      then level5+head never materializes child activations.
// ---------------------------------------------------------------------------

#define B_SZ 128

// ping-pong activations (device globals; allocation forbidden)
__device__ float g_actA[(size_t)B_SZ * 1024 * 64];   // 33.5 MB: l0,l2,l4 outs
__device__ float g_actB[(size_t)B_SZ * 256  * 64];   //  8.4 MB: l1,l3 outs
// WF[p][c][k][r] : 1024 * 4 * 48 * 16 floats = 12.6 MB
__device__ float g_wf[(size_t)1024 * 4 * 48 * 16];

// ---------------------------------------------------------------------------
// WF precompute: block = level-5 node p. WF[c][k][r] = sum_o W[k][o]*F_c[r][o]
// threads 256; threads 0..191 own a (c,k) pair and produce 16 r-values.
// ---------------------------------------------------------------------------
__global__ __launch_bounds__(256)
void qt_wf_kernel(const float* __restrict__ ftl, const float* __restrict__ ftr,
                  const float* __restrict__ fbl, const float* __restrict__ fbr,
                  const float* __restrict__ head_w, float* __restrict__ wf)
{
    __shared__ float w_s[48][64];
    __shared__ float F_s[4][16][64];

    const int p    = blockIdx.x;
    const int tid  = threadIdx.x;
    const int node = 341 + p;

    for (int k = tid; k < 48 * 64; k += 256)
        w_s[k >> 6][k & 63] = head_w[k];
    {
        const float* s0 = ftl + (size_t)node * 1024;
        const float* s1 = ftr + (size_t)node * 1024;
        const float* s2 = fbl + (size_t)node * 1024;
        const float* s3 = fbr + (size_t)node * 1024;
        for (int k = tid; k < 1024; k += 256) {
            F_s[0][k >> 6][k & 63] = s0[k];
            F_s[1][k >> 6][k & 63] = s1[k];
            F_s[2][k >> 6][k & 63] = s2[k];
            F_s[3][k >> 6][k & 63] = s3[k];
        }
    }
    __syncthreads();

    if (tid < 192) {
        const int c = tid / 48;
        const int k = tid - c * 48;

        float acc[16];
#pragma unroll
        for (int r = 0; r < 16; r++) acc[r] = 0.f;

#pragma unroll 1
        for (int o = 0; o < 64; o += 4) {
            float4 wv = *(const float4*)&w_s[k][o];
#pragma unroll
            for (int r = 0; r < 16; r++) {
                float4 f = *(const float4*)&F_s[c][r][o];
                acc[r] += wv.x * f.x + wv.y * f.y + wv.z * f.z + wv.w * f.w;
            }
        }
        float* dst = wf + ((size_t)p * 4 + c) * (48 * 16) + (size_t)k * 16;
#pragma unroll
        for (int r = 0; r < 16; r += 4)
            *(float4*)(dst + r) = make_float4(acc[r], acc[r+1], acc[r+2], acc[r+3]);
    }
}

// ---------------------------------------------------------------------------
// Levels 0..4: block = (node p, child c, batch-half q); 64 threads = batch.
// grid = n * 8.  Per-thread serial work: 1024 (lat) + 1024 (one child) FMA.
// ---------------------------------------------------------------------------
__global__ __launch_bounds__(64)
void qt_level(const float* __restrict__ xin, float* __restrict__ xout,
              const float* __restrict__ fin,
              const float* __restrict__ ftl, const float* __restrict__ ftr,
              const float* __restrict__ fbl, const float* __restrict__ fbr,
              const float* __restrict__ scale,
              int n, int off, int gside)
{
    __shared__ float fi_s[16][64];   // scale pre-folded
    __shared__ float F_s[16][64];    // this block's child only

    const int bid  = blockIdx.x;
    const int p    = bid >> 3;
    const int c    = (bid >> 1) & 3;
    const int q    = bid & 1;
    const int tid  = threadIdx.x;
    const int node = off + p;

    const float* Fc = (c == 0 ? ftl : c == 1 ? ftr : c == 2 ? fbl : fbr)
                      + (size_t)node * 1024;
    const float* fib = fin + (size_t)node * 1024;
    const float* scb = scale + (size_t)node * 16;

    for (int k = tid; k < 1024; k += 64) {
        fi_s[k >> 6][k & 63] = fib[k] * __ldg(&scb[k >> 6]);
        F_s [k >> 6][k & 63] = Fc[k];
    }
    __syncthreads();

    const int b = q * 64 + tid;
    const float* xp = xin + ((size_t)b * n + p) * 64;

    float lat[16];
#pragma unroll
    for (int r = 0; r < 16; r++) lat[r] = 0.f;
#pragma unroll 1
    for (int i = 0; i < 64; i += 4) {
        float4 xv = *(const float4*)(xp + i);
#pragma unroll
        for (int r = 0; r < 16; r++) {
            float4 f = *(const float4*)&fi_s[r][i];
            lat[r] += xv.x * f.x + xv.y * f.y + xv.z * f.z + xv.w * f.w;
        }
    }

    const int gr = p / gside;
    const int gc = p - gr * gside;
    const int cn = (2 * gr + (c >> 1)) * (2 * gside) + 2 * gc + (c & 1);
    float* op = xout + ((size_t)b * (4 * n) + cn) * 64;

#pragma unroll 1
    for (int o = 0; o < 64; o += 4) {
        float4 ov = *(const float4*)(xp + o);   // residual (L1 hit)
#pragma unroll
        for (int r = 0; r < 16; r++) {
            float4 f = *(const float4*)&F_s[r][o];
            float l = lat[r];
            ov.x += l * f.x; ov.y += l * f.y; ov.z += l * f.z; ov.w += l * f.w;
        }
        *(float4*)(op + o) = ov;
    }
}

// ---------------------------------------------------------------------------
// Fused level5 + head via WF. Block = level-5 parent p; 128 threads = batch.
//   lat = (x fi'^T)            1024 FMA
//   wx  = W x + b              3072 FMA   (shared by 4 children)
//   per child: y = wx + WF_c lat  (48x16)  768 FMA, write pixels directly.
// ---------------------------------------------------------------------------
__global__ __launch_bounds__(128)
void qt_l5_head(const float* __restrict__ xin,
                const float* __restrict__ fin, const float* __restrict__ scale,
                const float* __restrict__ wf,
                const float* __restrict__ head_w, const float* __restrict__ head_b,
                float* __restrict__ out)
{
    __shared__ float fi_s[16][64];
    __shared__ float w_s[48][64];
    __shared__ float wf_s[4][48][16];
    __shared__ float hb_s[48];

    const int p    = blockIdx.x;     // 0..1023
    const int tid  = threadIdx.x;    // batch
    const int node = 341 + p;

    {
        const float* fib = fin + (size_t)node * 1024;
        const float* scb = scale + (size_t)node * 16;
        for (int k = tid; k < 1024; k += 128)
            fi_s[k >> 6][k & 63] = fib[k] * __ldg(&scb[k >> 6]);
        for (int k = tid; k < 48 * 64; k += 128)
            w_s[k >> 6][k & 63] = head_w[k];
        const float* wfp = wf + (size_t)p * (4 * 48 * 16);
        float* wfs = (float*)wf_s;
        for (int k = tid; k < 4 * 48 * 16; k += 128)
            wfs[k] = wfp[k];
        if (tid < 48) hb_s[tid] = head_b[tid];
    }
    __syncthreads();

    const int b = tid;
    const float* xp = xin + ((size_t)b * 1024 + p) * 64;

    // lat
    float lat[16];
#pragma unroll
    for (int r = 0; r < 16; r++) lat[r] = 0.f;
#pragma unroll 1
    for (int i = 0; i < 64; i += 4) {
        float4 xv = *(const float4*)(xp + i);
#pragma unroll
        for (int r = 0; r < 16; r++) {
            float4 f = *(const float4*)&fi_s[r][i];
            lat[r] += xv.x * f.x + xv.y * f.y + xv.z * f.z + xv.w * f.w;
        }
    }

    // wx = W x + b  (shared across children)
    float wx[48];
#pragma unroll
    for (int k = 0; k < 48; k++) wx[k] = hb_s[k];
#pragma unroll 1
    for (int i = 0; i < 64; i += 4) {
        float4 xv = *(const float4*)(xp + i);   // L1 hit (second pass)
#pragma unroll
        for (int k = 0; k < 48; k++) {
            float4 wv = *(const float4*)&w_s[k][i];
            wx[k] += xv.x * wv.x + xv.y * wv.y + xv.z * wv.z + xv.w * wv.w;
        }
    }

    const int gr = p >> 5;
    const int gc = p & 31;

#pragma unroll 1
    for (int c = 0; c < 4; c++) {
        const int cn = (2 * gr + (c >> 1)) * 64 + 2 * gc + (c & 1);

        float acc[48];
#pragma unroll
        for (int k = 0; k < 48; k++) acc[k] = wx[k];

#pragma unroll
        for (int rs = 0; rs < 16; rs += 4) {
            const float l0 = lat[rs], l1 = lat[rs+1], l2 = lat[rs+2], l3 = lat[rs+3];
#pragma unroll
            for (int k = 0; k < 48; k++) {
                float4 f = *(const float4*)&wf_s[c][k][rs];
                acc[k] += l0 * f.x + l1 * f.y + l2 * f.z + l3 * f.w;
            }
        }

        // y[b, cn, k] -> pixels, k = pr*12 + pc*3 + oc
        const int sr = cn >> 6, sc = cn & 63;
#pragma unroll
        for (int oc = 0; oc < 3; oc++) {
#pragma unroll
            for (int pr = 0; pr < 4; pr++) {
                float4 v = make_float4(acc[pr * 12 + 0 + oc],
                                       acc[pr * 12 + 3 + oc],
                                       acc[pr * 12 + 6 + oc],
                                       acc[pr * 12 + 9 + oc]);
                size_t row = (size_t)(b * 3 + oc) * 256 + (sr * 4 + pr);
                *(float4*)(out + row * 256 + sc * 4) = v;
            }
        }
    }
}

// ---------------------------------------------------------------------------
extern "C" void kernel_launch(void* const* d_in, const int* in_sizes, int n_in,
                              void* d_out, int out_size)
{
    const float* x      = (const float*)d_in[0];
    const float* fin    = (const float*)d_in[1];
    const float* ftl    = (const float*)d_in[2];
    const float* ftr    = (const float*)d_in[3];
    const float* fbl    = (const float*)d_in[4];
    const float* fbr    = (const float*)d_in[5];
    const float* scale  = (const float*)d_in[6];
    const float* head_w = (const float*)d_in[7];
    const float* head_b = (const float*)d_in[8];
    float* out = (float*)d_out;

    float *bA, *bB, *wfb;
    cudaGetSymbolAddress((void**)&bA,  g_actA);
    cudaGetSymbolAddress((void**)&bB,  g_actB);
    cudaGetSymbolAddress((void**)&wfb, g_wf);

    // WF precompute (x-independent)
    qt_wf_kernel<<<1024, 256>>>(ftl, ftr, fbl, fbr, head_w, wfb);

    const int ns[5]   = {1, 4, 16, 64, 256};
    const int offs[5] = {0, 1, 5, 21, 85};
    const int gs[5]   = {1, 2, 4, 8, 16};

    const float* cur = x;
    for (int l = 0; l < 5; l++) {
        float* o = (l & 1) ? bB : bA;
        qt_level<<<ns[l] * 8, 64>>>(cur, o, fin, ftl, ftr, fbl, fbr, scale,
                                    ns[l], offs[l], gs[l]);
        cur = o;
    }

    qt_l5_head<<<1024, 128>>>(cur, fin, scale, wfb, head_w, head_b, out);
}